// round 1
// baseline (speedup 1.0000x reference)
#include <cuda_runtime.h>

// CommNet fused kernel: one CTA per batch element (grid = 1024).
// h, h0, A tiles (64 x 256 fp32) persist in SMEM across all 4 comm steps.
// x@W1 rewritten as h@(W1a - inv*W1b) + h0@W1c + bcast(inv * S@W1b).

#define HID   256
#define MAG   64
#define PAD   260          // row pitch (floats) for 64-row SMEM tiles; mult of 4
#define KT    16           // K-tile for weight streaming
#define STEPS 4
#define INVF  (1.0f/63.0f)

__global__ void __launch_bounds__(256, 1) commnet_kernel(
    const int*   __restrict__ ids,   // (B, 64)
    const float* __restrict__ W1,    // (768, 256) row-major
    const float* __restrict__ b1,    // (256)
    const float* __restrict__ W2,    // (256, 256)
    const float* __restrict__ b2,    // (256)
    const float* __restrict__ Wd,    // (256, 16)
    const float* __restrict__ bd,    // (16)
    const float* __restrict__ emb,   // (1000, 256)
    float*       __restrict__ out)   // (B, 64, 16)
{
    extern __shared__ float smem[];
    float* hS  = smem;                  // [64][PAD]
    float* h0S = hS  + MAG * PAD;       // [64][PAD]
    float* aS  = h0S + MAG * PAD;       // [64][PAD]
    float* bS  = aS  + MAG * PAD;       // [KT][256]
    float* Sv  = bS  + KT * HID;        // [256]
    float* Tv  = Sv  + HID;             // [256]

    const int b   = blockIdx.x;
    const int tid = threadIdx.x;
    const int ty  = tid >> 5;           // 0..7  : row group (8 rows)
    const int tx  = tid & 31;           // 0..31 : col group (8 cols)

    const int* myids = ids + b * MAG;

    // ---- gather embeddings into h and h0 ----
    for (int i = tid; i < MAG * (HID / 4); i += 256) {
        int row = i >> 6;               // 0..63
        int c4  = i & 63;               // 0..63 (float4 index)
        int aid = myids[row];
        float4 v = reinterpret_cast<const float4*>(emb + aid * HID)[c4];
        reinterpret_cast<float4*>(hS  + row * PAD)[c4] = v;
        reinterpret_cast<float4*>(h0S + row * PAD)[c4] = v;
    }

    const int brow = tid >> 4;          // 0..15 : Bsm row this thread loads
    const int bcol = (tid & 15) << 4;   // 0..240: Bsm col start (16 floats)

    for (int step = 0; step < STEPS; ++step) {
        __syncthreads();

        // ---- S[c] = sum_j h[j][c] ----
        {
            float s = 0.f;
            #pragma unroll 8
            for (int j = 0; j < MAG; ++j) s += hS[j * PAD + tid];
            Sv[tid] = s;
        }
        __syncthreads();

        // ---- Tv[c] = b1[c] + inv * (S @ W1b)[c], W1b = W1 rows 256..511 ----
        {
            const float* w = W1 + HID * HID + tid;
            float acc = 0.f;
            #pragma unroll 8
            for (int k = 0; k < HID; ++k) acc = fmaf(Sv[k], w[k * HID], acc);
            Tv[tid] = fmaf(acc, INVF, b1[tid]);
        }
        // (visibility of Tv covered by the first tile __syncthreads below)

        // ================= GEMM1: A = relu(h@W1eff + h0@W1c + Tv) ========
        float acc[8][8];
        #pragma unroll
        for (int i = 0; i < 8; ++i)
            #pragma unroll
            for (int j = 0; j < 8; ++j) acc[i][j] = 0.f;

        // pass A: h @ (W1a - inv*W1b)
        for (int k0 = 0; k0 < HID; k0 += KT) {
            __syncthreads();
            {
                const float4* g1 = reinterpret_cast<const float4*>(W1 + (k0 + brow) * HID + bcol);
                const float4* g2 = reinterpret_cast<const float4*>(W1 + (HID + k0 + brow) * HID + bcol);
                float4* dst = reinterpret_cast<float4*>(bS + brow * HID + bcol);
                #pragma unroll
                for (int q = 0; q < 4; ++q) {
                    float4 x = g1[q], y = g2[q];
                    dst[q] = make_float4(fmaf(-INVF, y.x, x.x), fmaf(-INVF, y.y, x.y),
                                         fmaf(-INVF, y.z, x.z), fmaf(-INVF, y.w, x.w));
                }
            }
            __syncthreads();
            #pragma unroll
            for (int kk = 0; kk < KT; ++kk) {
                float af[8];
                #pragma unroll
                for (int i = 0; i < 8; ++i) af[i] = hS[(ty * 8 + i) * PAD + k0 + kk];
                float4 p0 = reinterpret_cast<const float4*>(bS + kk * HID + tx * 8)[0];
                float4 p1 = reinterpret_cast<const float4*>(bS + kk * HID + tx * 8)[1];
                float bf[8] = {p0.x, p0.y, p0.z, p0.w, p1.x, p1.y, p1.z, p1.w};
                #pragma unroll
                for (int i = 0; i < 8; ++i)
                    #pragma unroll
                    for (int j = 0; j < 8; ++j) acc[i][j] = fmaf(af[i], bf[j], acc[i][j]);
            }
        }
        // pass B: h0 @ W1c (rows 512..767)
        for (int k0 = 0; k0 < HID; k0 += KT) {
            __syncthreads();
            {
                const float4* g = reinterpret_cast<const float4*>(W1 + (2 * HID + k0 + brow) * HID + bcol);
                float4* dst = reinterpret_cast<float4*>(bS + brow * HID + bcol);
                #pragma unroll
                for (int q = 0; q < 4; ++q) dst[q] = g[q];
            }
            __syncthreads();
            #pragma unroll
            for (int kk = 0; kk < KT; ++kk) {
                float af[8];
                #pragma unroll
                for (int i = 0; i < 8; ++i) af[i] = h0S[(ty * 8 + i) * PAD + k0 + kk];
                float4 p0 = reinterpret_cast<const float4*>(bS + kk * HID + tx * 8)[0];
                float4 p1 = reinterpret_cast<const float4*>(bS + kk * HID + tx * 8)[1];
                float bf[8] = {p0.x, p0.y, p0.z, p0.w, p1.x, p1.y, p1.z, p1.w};
                #pragma unroll
                for (int i = 0; i < 8; ++i)
                    #pragma unroll
                    for (int j = 0; j < 8; ++j) acc[i][j] = fmaf(af[i], bf[j], acc[i][j]);
            }
        }
        // epilogue1: aS = relu(acc + Tv)
        #pragma unroll
        for (int i = 0; i < 8; ++i)
            #pragma unroll
            for (int j = 0; j < 8; ++j) {
                float v = acc[i][j] + Tv[tx * 8 + j];
                aS[(ty * 8 + i) * PAD + tx * 8 + j] = v > 0.f ? v : 0.f;
            }

        // ================= GEMM2: h += aS @ W2 + b2 ======================
        #pragma unroll
        for (int i = 0; i < 8; ++i)
            #pragma unroll
            for (int j = 0; j < 8; ++j) acc[i][j] = 0.f;

        for (int k0 = 0; k0 < HID; k0 += KT) {
            __syncthreads();   // also makes aS writes visible on first iter
            {
                const float4* g = reinterpret_cast<const float4*>(W2 + (k0 + brow) * HID + bcol);
                float4* dst = reinterpret_cast<float4*>(bS + brow * HID + bcol);
                #pragma unroll
                for (int q = 0; q < 4; ++q) dst[q] = g[q];
            }
            __syncthreads();
            #pragma unroll
            for (int kk = 0; kk < KT; ++kk) {
                float af[8];
                #pragma unroll
                for (int i = 0; i < 8; ++i) af[i] = aS[(ty * 8 + i) * PAD + k0 + kk];
                float4 p0 = reinterpret_cast<const float4*>(bS + kk * HID + tx * 8)[0];
                float4 p1 = reinterpret_cast<const float4*>(bS + kk * HID + tx * 8)[1];
                float bf[8] = {p0.x, p0.y, p0.z, p0.w, p1.x, p1.y, p1.z, p1.w};
                #pragma unroll
                for (int i = 0; i < 8; ++i)
                    #pragma unroll
                    for (int j = 0; j < 8; ++j) acc[i][j] = fmaf(af[i], bf[j], acc[i][j]);
            }
        }
        // epilogue2: residual update (each h element owned by exactly one thread)
        #pragma unroll
        for (int i = 0; i < 8; ++i)
            #pragma unroll
            for (int j = 0; j < 8; ++j)
                hS[(ty * 8 + i) * PAD + tx * 8 + j] += acc[i][j] + b2[tx * 8 + j];
    }

    __syncthreads();
    // ---- logits: out[b][j][:] = h[j] @ Wd + bd ----
    {
        int j  = tid >> 2;              // agent row 0..63
        int q4 = tid & 3;               // which 4 actions
        float4 o = reinterpret_cast<const float4*>(bd)[q4];
        float ox = o.x, oy = o.y, oz = o.z, ow = o.w;
        #pragma unroll 8
        for (int k = 0; k < HID; ++k) {
            float hv = hS[j * PAD + k];
            float4 w = reinterpret_cast<const float4*>(Wd + k * 16)[q4];
            ox = fmaf(hv, w.x, ox); oy = fmaf(hv, w.y, oy);
            oz = fmaf(hv, w.z, oz); ow = fmaf(hv, w.w, ow);
        }
        reinterpret_cast<float4*>(out + (b * MAG + j) * 16)[q4] = make_float4(ox, oy, oz, ow);
    }
}

extern "C" void kernel_launch(void* const* d_in, const int* in_sizes, int n_in,
                              void* d_out, int out_size)
{
    // metadata order: agent_ids, emb, W1, b1, W2, b2, Wd, bd
    const int*   ids = (const int*)  d_in[0];
    const float* emb = (const float*)d_in[1];
    const float* W1  = (const float*)d_in[2];
    const float* b1  = (const float*)d_in[3];
    const float* W2  = (const float*)d_in[4];
    const float* b2  = (const float*)d_in[5];
    const float* Wd  = (const float*)d_in[6];
    const float* bd  = (const float*)d_in[7];
    float* out = (float*)d_out;

    const int B = in_sizes[0] / MAG;   // 1024

    const int smem_bytes = (3 * MAG * PAD + KT * HID + 2 * HID) * (int)sizeof(float);
    cudaFuncSetAttribute(commnet_kernel,
                         cudaFuncAttributeMaxDynamicSharedMemorySize, smem_bytes);

    commnet_kernel<<<B, 256, smem_bytes>>>(ids, W1, b1, W2, b2, Wd, bd, emb, out);
}